// round 10
// baseline (speedup 1.0000x reference)
#include <cuda_runtime.h>
#include <cstdint>

#define Bc 256
#define Tc 512
#define Cc 256
#define Lc 64
#define GSP 68            // padded gathered row (65 used)
#define CHUNK 64
#define NCHUNK (Tc / CHUNK)
#define LOG2E 1.4426950408889634f
#define LN2 0.6931471805599453f
#define ESENT (-100000)

__device__ float g_loss[Bc];

// warp-collective: softmax of one logits row + gather 65 label classes
// (linear probs) into SMEM. Full warp must call.
__device__ __forceinline__ void softmax_row(
    const float* __restrict__ rf, const int* __restrict__ s_tg,
    float* __restrict__ out, int lane)
{
    const float4* rp = (const float4*)rf;
    const float4 v0 = rp[lane];
    const float4 v1 = rp[lane + 32];

    float m = fmaxf(fmaxf(fmaxf(v0.x, v0.y), fmaxf(v0.z, v0.w)),
                    fmaxf(fmaxf(v1.x, v1.y), fmaxf(v1.z, v1.w)));
    #pragma unroll
    for (int o = 16; o; o >>= 1) m = fmaxf(m, __shfl_xor_sync(0xffffffffu, m, o));

    float s = exp2f((v0.x - m) * LOG2E) + exp2f((v0.y - m) * LOG2E)
            + exp2f((v0.z - m) * LOG2E) + exp2f((v0.w - m) * LOG2E)
            + exp2f((v1.x - m) * LOG2E) + exp2f((v1.y - m) * LOG2E)
            + exp2f((v1.z - m) * LOG2E) + exp2f((v1.w - m) * LOG2E);
    #pragma unroll
    for (int o = 16; o; o >>= 1) s += __shfl_xor_sync(0xffffffffu, s, o);

    const float l2s = __log2f(s);
    #pragma unroll
    for (int j = lane; j < 65; j += 32) {
        const int cls = j ? s_tg[j - 1] : 0;
        out[j] = exp2f((rf[cls] - m) * LOG2E - l2s);   // rf[cls] is L1-hot
    }
}

// ---------------------------------------------------------------------------
// Fused kernel: one block per batch row. Warp 0 = alpha consumer (linear
// domain, per-lane pow2 scaling, branchless renorm, zero MUFU in loop).
// Warps 1..7 = softmax producers filling the SMEM double buffer one chunk
// ahead. One __syncthreads per 64-step chunk.
// ---------------------------------------------------------------------------
__global__ __launch_bounds__(256) void ctc_fused_kernel(
    const float* __restrict__ logits,
    const int* __restrict__ targets,
    const int* __restrict__ in_len,
    const int* __restrict__ tgt_len)
{
    const int b    = blockIdx.x;
    const int tid  = threadIdx.x;
    const int wid  = tid >> 5;
    const int lane = tid & 31;

    __shared__ float stg[2][CHUNK * GSP];   // 34816 B double buffer
    __shared__ int   s_tg[Lc];
    __shared__ float fin_m[132];
    __shared__ int   fin_e[33];

    const int tlen = in_len[b];
    const float* __restrict__ lg = logits + (size_t)b * Tc * Cc;

    if (tid < Lc) s_tg[tid] = targets[b * Lc + tid];
    __syncthreads();

    // fill chunk 0 with all 8 warps
    {
        const int rows0 = (CHUNK < tlen) ? CHUNK : tlen;
        for (int r = wid; r < rows0; r += 8)
            softmax_row(lg + (size_t)r * Cc, s_tg, &stg[0][r * GSP], lane);
    }
    __syncthreads();

    // consumer state (only warp 0 uses it)
    float a0 = 0.f, a1 = 0.f, a2 = 0.f, a3 = 0.f, a4 = 0.f;
    int   E  = ESENT;
    float sk1f = 0.f, sk3f = 0.f;
    int   j1 = 1, j3 = 2;
    if (wid == 0) {
        j1 = 2 * lane + 1;
        j3 = 2 * lane + 2;
        if (lane > 0) sk1f = (s_tg[2 * lane] != s_tg[2 * lane - 1]) ? 1.f : 0.f;
        sk3f = (s_tg[2 * lane + 1] != s_tg[2 * lane]) ? 1.f : 0.f;
        if (lane == 0) { a0 = stg[0][0]; a1 = stg[0][1]; E = 0; }
    }

    int t = 1;
    #pragma unroll 1
    for (int c = 0; c < NCHUNK; ++c) {
        if (wid == 0) {
            // ---- consume chunk c ----
            const float* __restrict__ sp = stg[c & 1];
            const int tcend = ((c + 1) * CHUNK < tlen) ? (c + 1) * CHUNK : tlen;
            const float* q = sp + (t - c * CHUNK) * GSP;
            #pragma unroll 2
            for (; t < tcend; ++t, q += GSP) {
                const float lpb = q[0];
                const float lpA = q[j1];
                const float lpB = q[j3];

                float pm = __shfl_up_sync(0xffffffffu, a3, 1);  // alpha[4l-1]
                int   pe = __shfl_up_sync(0xffffffffu, E,  1);
                if (lane == 0) { pm = 0.f; pe = ESENT; }

                // unify scales (exact powers of two)
                const int eu = max(E, pe);
                const int dl = max(E  - eu, -127);
                const int dp = max(pe - eu, -127);
                const float sl  = __int_as_float((dl + 127) << 23);
                const float spf = __int_as_float((dp + 127) << 23);
                const float p = pm * spf;
                a0 *= sl; a1 *= sl; a2 *= sl; a3 *= sl; a4 *= sl;

                const float n0 = (a0 + p) * lpb;
                const float n1 = fmaf(sk1f, p,  a0 + a1) * lpA;
                const float n2 = (a1 + a2) * lpb;
                const float n3 = fmaf(sk3f, a1, a2 + a3) * lpB;
                a4 = (a3 + a4) * lpb;                   // state 128 (lane 31)

                // branchless exact renorm: mx==0 -> k=-127, sc=2^127, 0*sc=0
                const float m4 = (lane == 31) ? a4 : 0.f;
                const float mx = fmaxf(fmaxf(n0, n1), fmaxf(fmaxf(n2, n3), m4));
                const int k = (__float_as_int(mx) >> 23) - 127;
                const float sc = __int_as_float((127 - k) << 23); // 2^-k exact
                a0 = n0 * sc; a1 = n1 * sc; a2 = n2 * sc; a3 = n3 * sc; a4 *= sc;
                E = eu + k;
            }
        } else {
            // ---- produce chunk c+1 ----
            const int base = (c + 1) * CHUNK;
            const int rows = ((base + CHUNK) < tlen ? CHUNK : tlen - base);
            float* __restrict__ dst = stg[(c + 1) & 1];
            for (int r = wid - 1; r < rows; r += 7)
                softmax_row(lg + (size_t)(base + r) * Cc, s_tg,
                            dst + r * GSP, lane);
        }
        __syncthreads();
        if ((c + 1) * CHUNK >= tlen) break;
    }

    // warp 0 finalizes
    if (wid == 0) {
        fin_m[4 * lane + 0] = a0;
        fin_m[4 * lane + 1] = a1;
        fin_m[4 * lane + 2] = a2;
        fin_m[4 * lane + 3] = a3;
        fin_e[lane] = E;
        if (lane == 31) { fin_m[128] = a4; fin_e[32] = E; }
        __syncwarp();

        if (lane == 0) {
            const int tl = tgt_len[b];
            const int s1 = 2 * tl, s2 = 2 * tl - 1;
            const float m1 = fin_m[s1];  const int e1 = fin_e[s1 >> 2];
            const float m2 = fin_m[s2];  const int e2 = fin_e[s2 >> 2];
            const int eu = max(e1, e2);
            const float f1 = __int_as_float((max(e1 - eu, -127) + 127) << 23);
            const float f2 = __int_as_float((max(e2 - eu, -127) + 127) << 23);
            const float sum = m1 * f1 + m2 * f2;
            float loss = 0.f;
            if (sum > 0.f) {
                loss = -LN2 * (__log2f(sum) + (float)eu);
                if (!(loss < 1e20f)) loss = 0.f;   // zero_infinity / NaN guard
            }
            g_loss[b] = loss / (float)tl;
        }
    }
}

// ---------------------------------------------------------------------------
// deterministic mean over batch
// ---------------------------------------------------------------------------
__global__ __launch_bounds__(Bc) void reduce_kernel(float* __restrict__ out)
{
    const int tid = threadIdx.x;
    float v = g_loss[tid];
    #pragma unroll
    for (int o = 16; o; o >>= 1) v += __shfl_xor_sync(0xffffffffu, v, o);
    __shared__ float r[8];
    if ((tid & 31) == 0) r[tid >> 5] = v;
    __syncthreads();
    if (tid == 0) {
        float ssum = 0.f;
        #pragma unroll
        for (int i = 0; i < 8; i++) ssum += r[i];
        out[0] = ssum / (float)Bc;
    }
}

extern "C" void kernel_launch(void* const* d_in, const int* in_sizes, int n_in,
                              void* d_out, int out_size)
{
    const float* logits  = (const float*)d_in[0];   // [B,T,C] f32
    const int*   targets = (const int*)d_in[1];     // [B,L] i32
    const int*   in_len  = (const int*)d_in[2];     // [B] i32
    const int*   tgt_len = (const int*)d_in[3];     // [B] i32
    (void)in_sizes; (void)n_in; (void)out_size;

    ctc_fused_kernel<<<Bc, 256>>>(logits, targets, in_len, tgt_len);
    reduce_kernel<<<1, Bc>>>((float*)d_out);
}

// round 11
// speedup vs baseline: 1.7568x; 1.7568x over previous
#include <cuda_runtime.h>
#include <cstdint>

#define Bc 256
#define Tc 512
#define Cc 256
#define Lc 64
#define GSP 68            // padded gathered row (65 used)
#define CHUNK 64
#define NCHUNK (Tc / CHUNK)
#define NTHR 512
#define NPROD 15          // producer warps (wid 1..15)
#define LOG2E 1.4426950408889634f
#define LN2 0.6931471805599453f
#define ESENT (-100000)

__device__ float g_loss[Bc];
__device__ int   g_ctr;          // zero-init; reset by last block each launch

// warp-collective: softmax of one logits row + gather 65 label classes
// (linear probs) into SMEM. Full warp must call.
__device__ __forceinline__ void softmax_row(
    const float* __restrict__ rf, const int* __restrict__ s_tg,
    float* __restrict__ out, int lane)
{
    const float4* rp = (const float4*)rf;
    const float4 v0 = rp[lane];
    const float4 v1 = rp[lane + 32];

    float m = fmaxf(fmaxf(fmaxf(v0.x, v0.y), fmaxf(v0.z, v0.w)),
                    fmaxf(fmaxf(v1.x, v1.y), fmaxf(v1.z, v1.w)));
    #pragma unroll
    for (int o = 16; o; o >>= 1) m = fmaxf(m, __shfl_xor_sync(0xffffffffu, m, o));

    float s = exp2f((v0.x - m) * LOG2E) + exp2f((v0.y - m) * LOG2E)
            + exp2f((v0.z - m) * LOG2E) + exp2f((v0.w - m) * LOG2E)
            + exp2f((v1.x - m) * LOG2E) + exp2f((v1.y - m) * LOG2E)
            + exp2f((v1.z - m) * LOG2E) + exp2f((v1.w - m) * LOG2E);
    #pragma unroll
    for (int o = 16; o; o >>= 1) s += __shfl_xor_sync(0xffffffffu, s, o);

    const float l2s = __log2f(s);
    #pragma unroll
    for (int j = lane; j < 65; j += 32) {
        const int cls = j ? s_tg[j - 1] : 0;
        out[j] = exp2f((rf[cls] - m) * LOG2E - l2s);   // rf[cls] is L1-hot
    }
}

// one alpha step; DO_RENORM toggles the exact pow2 renormalization
#define ASTEP(QPTR, DO_RENORM) do {                                        \
    const float lpb = (QPTR)[0];                                           \
    const float lpA = (QPTR)[j1];                                          \
    const float lpB = (QPTR)[j3];                                          \
    float pm = __shfl_up_sync(0xffffffffu, a3, 1);                         \
    int   pe = __shfl_up_sync(0xffffffffu, E,  1);                         \
    if (lane == 0) { pm = 0.f; pe = ESENT; }                               \
    const int eu = max(E, pe);                                             \
    const int dl = max(E  - eu, -127);                                     \
    const int dp = max(pe - eu, -127);                                     \
    const float sl  = __int_as_float((dl + 127) << 23);                    \
    const float spf = __int_as_float((dp + 127) << 23);                    \
    const float p = pm * spf;                                              \
    a0 *= sl; a1 *= sl; a2 *= sl; a3 *= sl; a4 *= sl;                      \
    const float n0 = (a0 + p) * lpb;                                       \
    const float n1 = fmaf(sk1f, p,  a0 + a1) * lpA;                        \
    const float n2 = (a1 + a2) * lpb;                                      \
    const float n3 = fmaf(sk3f, a1, a2 + a3) * lpB;                        \
    a4 = (a3 + a4) * lpb;                                                  \
    if (DO_RENORM) {                                                       \
        const float m4 = (lane == 31) ? a4 : 0.f;                          \
        const float mx = fmaxf(fmaxf(n0, n1), fmaxf(fmaxf(n2, n3), m4));   \
        const int kk = (__float_as_int(mx) >> 23) - 127;                   \
        const float sc = __int_as_float((127 - kk) << 23);                 \
        a0 = n0 * sc; a1 = n1 * sc; a2 = n2 * sc; a3 = n3 * sc; a4 *= sc;  \
        E = eu + kk;                                                       \
    } else {                                                               \
        a0 = n0; a1 = n1; a2 = n2; a3 = n3;                                \
        E = eu;                                                            \
    }                                                                      \
} while (0)

// ---------------------------------------------------------------------------
// Fused kernel: one block per batch row. Warp 0 = alpha consumer (linear
// domain, per-lane pow2 scaling, renorm every 2nd step, zero MUFU in loop).
// Warps 1..15 = softmax producers filling the SMEM double buffer one chunk
// ahead. One __syncthreads per 64-step chunk. Last block folds the mean.
// ---------------------------------------------------------------------------
__global__ __launch_bounds__(NTHR) void ctc_fused_kernel(
    const float* __restrict__ logits,
    const int* __restrict__ targets,
    const int* __restrict__ in_len,
    const int* __restrict__ tgt_len,
    float* __restrict__ d_out)
{
    const int b    = blockIdx.x;
    const int tid  = threadIdx.x;
    const int wid  = tid >> 5;
    const int lane = tid & 31;

    __shared__ float stg[2][CHUNK * GSP];   // 34816 B double buffer
    __shared__ int   s_tg[Lc];
    __shared__ float fin_m[132];
    __shared__ int   fin_e[33];
    __shared__ int   s_last;

    const int tlen = in_len[b];
    const float* __restrict__ lg = logits + (size_t)b * Tc * Cc;

    if (tid < Lc) s_tg[tid] = targets[b * Lc + tid];
    __syncthreads();

    // fill chunk 0 with all 16 warps
    {
        const int rows0 = (CHUNK < tlen) ? CHUNK : tlen;
        #pragma unroll 2
        for (int r = wid; r < rows0; r += 16)
            softmax_row(lg + (size_t)r * Cc, s_tg, &stg[0][r * GSP], lane);
    }
    __syncthreads();

    // consumer state (only warp 0 uses it)
    float a0 = 0.f, a1 = 0.f, a2 = 0.f, a3 = 0.f, a4 = 0.f;
    int   E  = ESENT;
    float sk1f = 0.f, sk3f = 0.f;
    int   j1 = 1, j3 = 2;
    if (wid == 0) {
        j1 = 2 * lane + 1;
        j3 = 2 * lane + 2;
        if (lane > 0) sk1f = (s_tg[2 * lane] != s_tg[2 * lane - 1]) ? 1.f : 0.f;
        sk3f = (s_tg[2 * lane + 1] != s_tg[2 * lane]) ? 1.f : 0.f;
        if (lane == 0) { a0 = stg[0][0]; a1 = stg[0][1]; E = 0; }
    }

    int t = 1;
    #pragma unroll 1
    for (int c = 0; c < NCHUNK; ++c) {
        if (wid == 0) {
            // ---- consume chunk c (renorm every 2nd step) ----
            const float* __restrict__ sp = stg[c & 1];
            const int tcend = ((c + 1) * CHUNK < tlen) ? (c + 1) * CHUNK : tlen;
            const float* q = sp + (t - c * CHUNK) * GSP;
            #pragma unroll 1
            for (; t + 1 < tcend; t += 2, q += 2 * GSP) {
                ASTEP(q, false);
                ASTEP(q + GSP, true);
            }
            if (t < tcend) { ASTEP(q, true); ++t; }
        } else {
            // ---- produce chunk c+1 ----
            const int base = (c + 1) * CHUNK;
            const int rows = ((base + CHUNK) < tlen ? CHUNK : tlen - base);
            float* __restrict__ dst = stg[(c + 1) & 1];
            #pragma unroll 2
            for (int r = wid - 1; r < rows; r += NPROD)
                softmax_row(lg + (size_t)(base + r) * Cc, s_tg,
                            dst + r * GSP, lane);
        }
        __syncthreads();
        if ((c + 1) * CHUNK >= tlen) break;
    }

    // warp 0 finalizes this batch row
    if (wid == 0) {
        fin_m[4 * lane + 0] = a0;
        fin_m[4 * lane + 1] = a1;
        fin_m[4 * lane + 2] = a2;
        fin_m[4 * lane + 3] = a3;
        fin_e[lane] = E;
        if (lane == 31) { fin_m[128] = a4; fin_e[32] = E; }
        __syncwarp();

        if (lane == 0) {
            const int tl = tgt_len[b];
            const int s1 = 2 * tl, s2 = 2 * tl - 1;
            const float m1 = fin_m[s1];  const int e1 = fin_e[s1 >> 2];
            const float m2 = fin_m[s2];  const int e2 = fin_e[s2 >> 2];
            const int eu = max(e1, e2);
            const float f1 = __int_as_float((max(e1 - eu, -127) + 127) << 23);
            const float f2 = __int_as_float((max(e2 - eu, -127) + 127) << 23);
            const float sum = m1 * f1 + m2 * f2;
            float loss = 0.f;
            if (sum > 0.f) {
                loss = -LN2 * (__log2f(sum) + (float)eu);
                if (!(loss < 1e20f)) loss = 0.f;   // zero_infinity / NaN guard
            }
            g_loss[b] = loss / (float)tl;
        }
    }

    // last finished block computes the batch mean (deterministic fixed-order
    // reduction by one warp) and resets the counter for the next replay
    if (tid == 0) {
        __threadfence();
        s_last = (atomicAdd(&g_ctr, 1) == Bc - 1);
    }
    __syncthreads();
    if (s_last && wid == 0) {
        __threadfence();
        float v = 0.f;
        #pragma unroll
        for (int i = 0; i < Bc / 32; ++i) v += g_loss[lane + i * 32];
        #pragma unroll
        for (int o = 16; o; o >>= 1) v += __shfl_xor_sync(0xffffffffu, v, o);
        if (lane == 0) { d_out[0] = v / (float)Bc; g_ctr = 0; }
    }
}

extern "C" void kernel_launch(void* const* d_in, const int* in_sizes, int n_in,
                              void* d_out, int out_size)
{
    const float* logits  = (const float*)d_in[0];   // [B,T,C] f32
    const int*   targets = (const int*)d_in[1];     // [B,L] i32
    const int*   in_len  = (const int*)d_in[2];     // [B] i32
    const int*   tgt_len = (const int*)d_in[3];     // [B] i32
    (void)in_sizes; (void)n_in; (void)out_size;

    ctc_fused_kernel<<<Bc, NTHR>>>(logits, targets, in_len, tgt_len,
                                   (float*)d_out);
}